// round 14
// baseline (speedup 1.0000x reference)
#include <cuda_runtime.h>
#include <cuda_fp16.h>
#include <cstdint>

// ---------------------------------------------------------------------------
// Problem constants
// ---------------------------------------------------------------------------
#define D_MODEL 4096
#define HIDDEN  16384
#define N_TOK   4096

// Scratch (device globals: allocation-free rule)
__device__ __align__(16) __half        g_Xh[(size_t)N_TOK * D_MODEL];   // x in fp16
__device__ __align__(16) unsigned char g_W1p[(size_t)HIDDEN * D_MODEL]; // frag-order bytes (v+8)
__device__ __align__(16) unsigned char g_W2p[(size_t)D_MODEL * HIDDEN];
__device__ __align__(16) __half        g_H [(size_t)N_TOK * HIDDEN];    // hidden acts fp16

// ---------------------------------------------------------------------------
// Helpers
// ---------------------------------------------------------------------------
__device__ __forceinline__ uint32_t smem_u32(const void* p) {
    uint32_t a;
    asm("{ .reg .u64 t; cvta.to.shared.u64 t, %1; cvt.u32.u64 %0, t; }" : "=r"(a) : "l"(p));
    return a;
}

#define LDMATRIX_X4(r0, r1, r2, r3, addr) \
    asm volatile("ldmatrix.sync.aligned.m8n8.x4.shared.b16 {%0,%1,%2,%3}, [%4];" \
                 : "=r"(r0), "=r"(r1), "=r"(r2), "=r"(r3) : "r"(addr))

#define MMA_16816(c0, c1, c2, c3, a0, a1, a2, a3, b0, b1) \
    asm volatile("mma.sync.aligned.m16n8k16.row.col.f32.f16.f16.f32 " \
                 "{%0,%1,%2,%3}, {%4,%5,%6,%7}, {%8,%9}, {%0,%1,%2,%3};" \
                 : "+f"(c0), "+f"(c1), "+f"(c2), "+f"(c3) \
                 : "r"(a0), "r"(a1), "r"(a2), "r"(a3), "r"(b0), "r"(b1))

#define CP_ASYNC16(smaddr, gptr) \
    asm volatile("cp.async.cg.shared.global [%0], [%1], 16;" \
                 :: "r"(smaddr), "l"(gptr) : "memory")
#define CP_COMMIT() asm volatile("cp.async.commit_group;" ::: "memory")
#define CP_WAIT1()  asm volatile("cp.async.wait_group 1;" ::: "memory")

// one byte-stored (v+8) pair -> half2 of exact (v) values:
// prmt splices bytes with 0x64 exponent -> (0x6400|(v+8)) = 1032+v ; hsub 1032.
__device__ __forceinline__ uint32_t dq8(uint32_t comp, uint32_t sel) {
    uint32_t u = __byte_perm(comp, 0x64646464u, sel);
    const uint32_t OFF = 0x64086408u;
    __half2 a = *reinterpret_cast<__half2*>(&u);
    __half2 r = __hsub2(a, *reinterpret_cast<const __half2*>(&OFF));
    return *reinterpret_cast<uint32_t*>(&r);
}

// HW tanh (MUFU.TANH, sm_75+): 1 instruction vs ~40 for libm tanhf.
__device__ __forceinline__ float tanh_hw(float x) {
    float y;
    asm("tanh.approx.f32 %0, %1;" : "=f"(y) : "f"(x));
    return y;
}

__device__ __forceinline__ float gelu_tanh(float v) {
    float t = tanh_hw(0.7978845608028654f * (v + 0.044715f * v * v * v));
    return 0.5f * v * (1.0f + t);
}

// ---------------------------------------------------------------------------
// Phase 0 kernels
// ---------------------------------------------------------------------------
__global__ void convert_x_kernel(const float* __restrict__ x) {
    size_t i = (size_t)blockIdx.x * blockDim.x + threadIdx.x;  // one float4 each
    float4 v = reinterpret_cast<const float4*>(x)[i];
    __half2 a = __floats2half2_rn(v.x, v.y);
    __half2 b = __floats2half2_rn(v.z, v.w);
    uint2 u;
    u.x = *reinterpret_cast<uint32_t*>(&a);
    u.y = *reinterpret_cast<uint32_t*>(&b);
    reinterpret_cast<uint2*>(g_Xh)[i] = u;
}

// Repack weights into UNPACKED (v+8 bytes) MMA-fragment order.
// Chunk key (nb32 = n-block of 32 rows, kb32 = k-block of 32) = 1KB:
//   word index within chunk = pr*128 + lane*4 + c, pr in {0,1}, c in {0..3}
//   c -> (nf = pr*2 + (c>>1), s = c&1); group g = nb32*4+nf; row = g*8 + (lane>>2)
//   word bytes (t = lane&3, k rel kb32*32): v+8 at k = 16s+2t, 16s+2t+1, 16s+8+2t, 16s+8+2t+1
// So comp's bytes (0,1) are the mma b0 pair and (2,3) the b1 pair for k16-step s.
__global__ void repack_b_kernel(const int* __restrict__ in, int which, int K, int klog) {
    unsigned char* outb = which ? g_W2p : g_W1p;
    size_t W = (size_t)blockIdx.x * blockDim.x + threadIdx.x;  // one output word each
    const int c = (int)(W & 3);
    const int lane = (int)((W >> 2) & 31);
    const int pr = (int)((W >> 7) & 1);
    const size_t rest = W >> 8;
    const int kchunks = K >> 5;
    const int kb32 = (int)(rest & (size_t)(kchunks - 1));
    const size_t nb32 = rest >> klog;
    const int nf = pr * 2 + (c >> 1);
    const int s = c & 1;
    const int t = lane & 3;
    const size_t row = (nb32 * 4 + nf) * 8 + (lane >> 2);
    const int* src = in + row * (size_t)(K >> 1) + kb32 * 16 + 8 * s + t;
    uint32_t p0 = (uint32_t)src[0];
    uint32_t p1 = (uint32_t)src[4];
    uint32_t word = ((p0 >> 4) & 15u) | ((p0 & 15u) << 8) |
                    (((p1 >> 4) & 15u) << 16) | ((p1 & 15u) << 24);
    reinterpret_cast<uint32_t*>(outb)[W] = word;
}

// ---------------------------------------------------------------------------
// GEMM: C[m,n] = sum_k A[m,k] * W[n,k] ; epilogue applies scales[n] (+gelu)
// MODE 0: gelu(scale*acc) -> half  (gemm1)    MODE 1: scale*acc -> float (gemm2)
// A fp16 [Mtot,K] row-major; Bp frag-ordered (v+8) bytes (see repack).
// CTA tile 64x128, BK=64. 128 thr = 4 warps as 1(m) x 4(n); warp tile 64x32.
// 4 CTAs/SM (16 warps) -> 4 independent barrier domains per SM.
// B is warp-private: warp w cp.asyncs and reads its own 32-row n-seg.
// 3-stage cp.async pipeline (prefetch depth 2, wait_group 1), 1 barrier/iter.
// A: cp.async -> SW128 smem -> ldmatrix. B: cp.async bytes -> LDS.128 ->
// PRMT+HSUB2 register dequant -> MMA operands.
// Stage layout (16384B each): A @ +0 (8KB), B @ +8192 (8KB). Total 48KB.
// ---------------------------------------------------------------------------
#define SMEM_DYN (3 * 16384 + 1024)

template <int MODE>
__device__ __forceinline__ void gemm_body(const __half* __restrict__ A,
                                          const unsigned char* __restrict__ Bp,
                                          const float* __restrict__ scales,
                                          int K, __half* __restrict__ outH,
                                          float* __restrict__ outF, int ldOut) {
    extern __shared__ unsigned char dsm_raw[];
    const int tid = threadIdx.x;
    const int w = tid >> 5, lane = tid & 31;

    const uint32_t raw = smem_u32(dsm_raw);
    const uint32_t base = (raw + 1023u) & ~1023u;
    unsigned char* sptr = dsm_raw + (base - raw);

    const int m0 = blockIdx.y * 64;
    const int n0 = blockIdx.x * 128;
    const int kIters = K >> 6;
    const int kchunks = K >> 5;

    // ---- A cp.async: 512 16B chunks / 128 thr = 4 each; rows (tid>>3)+16j ----
    const int ar = tid >> 3;                 // 0..15
    const int ac = tid & 7;                  // 16B chunk in 128B row
    const uint32_t asw = (uint32_t)((ac * 16) ^ ((ar & 7) << 4));  // rows differ by 16 -> same
    const size_t agq = __cvta_generic_to_global(A + (size_t)(m0 + ar) * K + ac * 8);

    // ---- B cp.async: warp-private seg (2KB/iter); thread does 64B ----
    const size_t bgq = __cvta_generic_to_global(
        Bp + ((size_t)(n0 / 32 + w) * kchunks) * 1024 + lane * 64);
    const uint32_t bdst = (uint32_t)(w * 2048 + lane * 64);

    // ---- A ldmatrix lane addressing ----
    const uint32_t lxor = (uint32_t)((lane & 7) << 4);
    const uint32_t aRow = (uint32_t)((lane & 15) * 128);
    const uint32_t akb = (uint32_t)(((lane >> 4) & 1) * 16);

    float acc[4][4][4];
#pragma unroll
    for (int i = 0; i < 4; ++i)
#pragma unroll
        for (int j = 0; j < 4; ++j)
#pragma unroll
            for (int e = 0; e < 4; ++e) acc[i][j][e] = 0.0f;

    const uint32_t soff[3] = { 0u, 16384u, 32768u };

    // stage issue: A tile (64 rows x 64 k-cols) + B seg bytes for iteration ii
    auto issue_stage = [&](int ii, uint32_t so) {
        const int k0 = ii << 6;
#pragma unroll
        for (int j = 0; j < 4; ++j)
            CP_ASYNC16(base + so + (uint32_t)((ar + 16 * j) * 128) + asw,
                       (const void*)(agq + ((size_t)(16 * j) * K + k0) * sizeof(__half)));
        const size_t bs = bgq + (size_t)ii * 2048;
#pragma unroll
        for (int i = 0; i < 4; ++i)
            CP_ASYNC16(base + so + 8192u + bdst + (uint32_t)(i * 16),
                       (const void*)(bs + i * 16));
    };

    // ---- prologue: stages 0,1 in flight ----
    issue_stage(0, soff[0]); CP_COMMIT();
    issue_stage(1, soff[1]); CP_COMMIT();

    int p = 0;
    for (int it = 0; it < kIters; ++it) {
        CP_WAIT1();        // stage p's group complete (1 iter of slack)
        __syncthreads();   // 4-warp barrier; stage (p+2)%3 readers done

        if (it + 2 < kIters) issue_stage(it + 2, soff[p == 0 ? 2 : p - 1]);
        CP_COMMIT();       // always commit (possibly empty) to keep group count uniform

        // ---- compute from stage p: 2 k32-blocks x 2 k16-steps ----
        const uint32_t so = soff[p];
        const uint32_t sA = base + so;
        const unsigned char* sB = sptr + so + 8192 + w * 2048;
#pragma unroll
        for (int kb = 0; kb < 2; ++kb) {
            uint4 q0 = *reinterpret_cast<const uint4*>(sB + kb * 1024 + lane * 16);
            uint4 q1 = *reinterpret_cast<const uint4*>(sB + kb * 1024 + 512 + lane * 16);
#pragma unroll
            for (int h = 0; h < 2; ++h) {
                uint32_t comp[4];
                comp[0] = h ? q0.y : q0.x;
                comp[1] = h ? q0.w : q0.z;
                comp[2] = h ? q1.y : q1.x;
                comp[3] = h ? q1.w : q1.z;
                uint32_t b0[4], b1[4];
#pragma unroll
                for (int nf = 0; nf < 4; ++nf) {
                    b0[nf] = dq8(comp[nf], 0x4140u);
                    b1[nf] = dq8(comp[nf], 0x4342u);
                }
                const int s = kb * 2 + h;
                const uint32_t ca = ((uint32_t)(s * 32) + akb) ^ lxor;
                uint32_t af[4][4];
#pragma unroll
                for (int mf = 0; mf < 4; ++mf)
                    LDMATRIX_X4(af[mf][0], af[mf][1], af[mf][2], af[mf][3],
                                sA + aRow + (uint32_t)(mf * 16 * 128) + ca);
#pragma unroll
                for (int mf = 0; mf < 4; ++mf)
#pragma unroll
                    for (int nf = 0; nf < 4; ++nf)
                        MMA_16816(acc[mf][nf][0], acc[mf][nf][1],
                                  acc[mf][nf][2], acc[mf][nf][3],
                                  af[mf][0], af[mf][1], af[mf][2], af[mf][3],
                                  b0[nf], b1[nf]);
            }
        }
        p = (p == 2) ? 0 : p + 1;
    }

    // ---- epilogue: scales (+gelu), direct gmem stores ----
    const int mrow0 = m0 + (lane >> 2);
    const int ncol0 = n0 + w * 32 + (lane & 3) * 2;
#pragma unroll
    for (int nf = 0; nf < 4; ++nf) {
        const int col = ncol0 + nf * 8;
        const float s0 = __ldg(scales + col);
        const float s1 = __ldg(scales + col + 1);
#pragma unroll
        for (int mf = 0; mf < 4; ++mf) {
            const int r = mrow0 + mf * 16;
            float v0 = acc[mf][nf][0] * s0, v1 = acc[mf][nf][1] * s1;
            float v2 = acc[mf][nf][2] * s0, v3 = acc[mf][nf][3] * s1;
            if (MODE == 0) {
                __half2 h0 = __floats2half2_rn(gelu_tanh(v0), gelu_tanh(v1));
                __half2 h1 = __floats2half2_rn(gelu_tanh(v2), gelu_tanh(v3));
                *reinterpret_cast<__half2*>(outH + (size_t)r * ldOut + col) = h0;
                *reinterpret_cast<__half2*>(outH + (size_t)(r + 8) * ldOut + col) = h1;
            } else {
                *reinterpret_cast<float2*>(outF + (size_t)r * ldOut + col) = make_float2(v0, v1);
                *reinterpret_cast<float2*>(outF + (size_t)(r + 8) * ldOut + col) = make_float2(v2, v3);
            }
        }
    }
}

__global__ void __launch_bounds__(128, 4)
gemm1_kernel(const float* __restrict__ scales) {
    gemm_body<0>(g_Xh, g_W1p, scales, D_MODEL, g_H, nullptr, HIDDEN);
}

__global__ void __launch_bounds__(128, 4)
gemm2_kernel(const float* __restrict__ scales, float* __restrict__ out) {
    gemm_body<1>(g_H, g_W2p, scales, HIDDEN, nullptr, out, D_MODEL);
}

// ---------------------------------------------------------------------------
// Launch
// ---------------------------------------------------------------------------
extern "C" void kernel_launch(void* const* d_in, const int* in_sizes, int n_in,
                              void* d_out, int out_size) {
    const float* x    = (const float*)d_in[0];
    const int*   fc1p = (const int*)d_in[1];
    const float* s1   = (const float*)d_in[2];
    const int*   fc2p = (const int*)d_in[3];
    const float* s2   = (const float*)d_in[4];
    float* out = (float*)d_out;

    cudaFuncSetAttribute(gemm1_kernel, cudaFuncAttributeMaxDynamicSharedMemorySize, SMEM_DYN);
    cudaFuncSetAttribute(gemm2_kernel, cudaFuncAttributeMaxDynamicSharedMemorySize, SMEM_DYN);

    convert_x_kernel<<<(N_TOK * (size_t)D_MODEL) / 4 / 256, 256>>>(x);
    // repack: one thread per output word = N*K/4 words per matrix
    repack_b_kernel<<<((size_t)HIDDEN * D_MODEL / 4) / 256, 256>>>(fc1p, 0, D_MODEL, 7);
    repack_b_kernel<<<((size_t)D_MODEL * HIDDEN / 4) / 256, 256>>>(fc2p, 1, HIDDEN, 9);

    gemm1_kernel<<<dim3(HIDDEN / 128, N_TOK / 64), 128, SMEM_DYN>>>(s1);
    gemm2_kernel<<<dim3(D_MODEL / 128, N_TOK / 64), 128, SMEM_DYN>>>(s2, out);
}

// round 15
// speedup vs baseline: 1.0410x; 1.0410x over previous
#include <cuda_runtime.h>
#include <cuda_fp16.h>
#include <cstdint>

// ---------------------------------------------------------------------------
// Problem constants
// ---------------------------------------------------------------------------
#define D_MODEL 4096
#define HIDDEN  16384
#define N_TOK   4096

// Scratch (device globals: allocation-free rule)
__device__ __align__(16) __half        g_Xh[(size_t)N_TOK * D_MODEL];   // x in fp16
__device__ __align__(16) unsigned char g_W1p[(size_t)HIDDEN * D_MODEL]; // frag-order bytes (v+8)
__device__ __align__(16) unsigned char g_W2p[(size_t)D_MODEL * HIDDEN];
__device__ __align__(16) __half        g_H [(size_t)N_TOK * HIDDEN];    // hidden acts fp16

// ---------------------------------------------------------------------------
// Helpers
// ---------------------------------------------------------------------------
__device__ __forceinline__ uint32_t smem_u32(const void* p) {
    uint32_t a;
    asm("{ .reg .u64 t; cvta.to.shared.u64 t, %1; cvt.u32.u64 %0, t; }" : "=r"(a) : "l"(p));
    return a;
}

#define LDMATRIX_X4(r0, r1, r2, r3, addr) \
    asm volatile("ldmatrix.sync.aligned.m8n8.x4.shared.b16 {%0,%1,%2,%3}, [%4];" \
                 : "=r"(r0), "=r"(r1), "=r"(r2), "=r"(r3) : "r"(addr))

#define MMA_16816(c0, c1, c2, c3, a0, a1, a2, a3, b0, b1) \
    asm volatile("mma.sync.aligned.m16n8k16.row.col.f32.f16.f16.f32 " \
                 "{%0,%1,%2,%3}, {%4,%5,%6,%7}, {%8,%9}, {%0,%1,%2,%3};" \
                 : "+f"(c0), "+f"(c1), "+f"(c2), "+f"(c3) \
                 : "r"(a0), "r"(a1), "r"(a2), "r"(a3), "r"(b0), "r"(b1))

#define CP_ASYNC16(smaddr, gptr) \
    asm volatile("cp.async.cg.shared.global [%0], [%1], 16;" \
                 :: "r"(smaddr), "l"(gptr) : "memory")
#define CP_COMMIT() asm volatile("cp.async.commit_group;" ::: "memory")
#define CP_WAIT2()  asm volatile("cp.async.wait_group 2;" ::: "memory")

// one byte-stored (v+8) pair -> half2 of exact (v) values:
// prmt splices bytes with 0x64 exponent -> (0x6400|(v+8)) = 1032+v ; hsub 1032.
__device__ __forceinline__ uint32_t dq8(uint32_t comp, uint32_t sel) {
    uint32_t u = __byte_perm(comp, 0x64646464u, sel);
    const uint32_t OFF = 0x64086408u;
    __half2 a = *reinterpret_cast<__half2*>(&u);
    __half2 r = __hsub2(a, *reinterpret_cast<const __half2*>(&OFF));
    return *reinterpret_cast<uint32_t*>(&r);
}

// HW tanh (MUFU.TANH, sm_75+): 1 instruction vs ~40 for libm tanhf.
__device__ __forceinline__ float tanh_hw(float x) {
    float y;
    asm("tanh.approx.f32 %0, %1;" : "=f"(y) : "f"(x));
    return y;
}

__device__ __forceinline__ float gelu_tanh(float v) {
    float t = tanh_hw(0.7978845608028654f * (v + 0.044715f * v * v * v));
    return 0.5f * v * (1.0f + t);
}

// ---------------------------------------------------------------------------
// Phase 0 kernels
// ---------------------------------------------------------------------------
__global__ void convert_x_kernel(const float* __restrict__ x) {
    size_t i = (size_t)blockIdx.x * blockDim.x + threadIdx.x;  // one float4 each
    float4 v = reinterpret_cast<const float4*>(x)[i];
    __half2 a = __floats2half2_rn(v.x, v.y);
    __half2 b = __floats2half2_rn(v.z, v.w);
    uint2 u;
    u.x = *reinterpret_cast<uint32_t*>(&a);
    u.y = *reinterpret_cast<uint32_t*>(&b);
    reinterpret_cast<uint2*>(g_Xh)[i] = u;
}

// Repack weights into UNPACKED (v+8 bytes) MMA-fragment order.
// Chunk key (nb32 = n-block of 32 rows, kb32 = k-block of 32) = 1KB:
//   word index within chunk = pr*128 + lane*4 + c, pr in {0,1}, c in {0..3}
//   c -> (nf = pr*2 + (c>>1), s = c&1); group g = nb32*4+nf; row = g*8 + (lane>>2)
//   word bytes (t = lane&3, k rel kb32*32): v+8 at k = 16s+2t, 16s+2t+1, 16s+8+2t, 16s+8+2t+1
// So comp's bytes (0,1) are the mma b0 pair and (2,3) the b1 pair for k16-step s.
__global__ void repack_b_kernel(const int* __restrict__ in, int which, int K, int klog) {
    unsigned char* outb = which ? g_W2p : g_W1p;
    size_t W = (size_t)blockIdx.x * blockDim.x + threadIdx.x;  // one output word each
    const int c = (int)(W & 3);
    const int lane = (int)((W >> 2) & 31);
    const int pr = (int)((W >> 7) & 1);
    const size_t rest = W >> 8;
    const int kchunks = K >> 5;
    const int kb32 = (int)(rest & (size_t)(kchunks - 1));
    const size_t nb32 = rest >> klog;
    const int nf = pr * 2 + (c >> 1);
    const int s = c & 1;
    const int t = lane & 3;
    const size_t row = (nb32 * 4 + nf) * 8 + (lane >> 2);
    const int* src = in + row * (size_t)(K >> 1) + kb32 * 16 + 8 * s + t;
    uint32_t p0 = (uint32_t)src[0];
    uint32_t p1 = (uint32_t)src[4];
    uint32_t word = ((p0 >> 4) & 15u) | ((p0 & 15u) << 8) |
                    (((p1 >> 4) & 15u) << 16) | ((p1 & 15u) << 24);
    reinterpret_cast<uint32_t*>(outb)[W] = word;
}

// ---------------------------------------------------------------------------
// GEMM: C[m,n] = sum_k A[m,k] * W[n,k] ; epilogue applies scales[n] (+gelu)
// MODE 0: gelu(scale*acc) -> half via smem-staged coalesced stores (gemm1)
// MODE 1: scale*acc -> float direct (gemm2; float2 quads already coalesce)
// A fp16 [Mtot,K] row-major; Bp frag-ordered (v+8) bytes (see repack).
// CTA tile 128x128, BK=64. 256 thr = 8 warps as 2(m) x 4(n); warp tile 64x32.
// 4-stage cp.async pipeline (prefetch depth 3, wait_group 2), 1 barrier/iter.
// Stage layout (24576B each): A @ +0 (16KB), B @ +16384 (8KB). Total 96KB.
// MODE 0 epilogue stages the 128x128 half tile at pitch 272B in stages 0-1
// (p_last = 3 since kIters % 4 == 0, so no overlap with final reads).
// ---------------------------------------------------------------------------
#define SMEM_DYN (4 * 24576 + 1024)
#define EPI_PITCH 272   // 128 cols * 2B = 256B data, padded to 16B-aligned 272B

template <int MODE>
__device__ __forceinline__ void gemm_body(const __half* __restrict__ A,
                                          const unsigned char* __restrict__ Bp,
                                          const float* __restrict__ scales,
                                          int K, __half* __restrict__ outH,
                                          float* __restrict__ outF, int ldOut) {
    extern __shared__ unsigned char dsm_raw[];
    const int tid = threadIdx.x;
    const int w = tid >> 5, lane = tid & 31;
    const int wm = w & 1, wn = w >> 1;

    const uint32_t raw = smem_u32(dsm_raw);
    const uint32_t base = (raw + 1023u) & ~1023u;
    unsigned char* sptr = dsm_raw + (base - raw);

    const int m0 = blockIdx.y * 128;
    const int n0 = blockIdx.x * 128;
    const int kIters = K >> 6;
    const int kchunks = K >> 5;

    // ---- A cp.async: 1024 16B chunks / 256 thr = 4 each; rows (tid>>3)+32j ----
    const int ar = tid >> 3;                 // 0..31
    const int ac = tid & 7;                  // 16B chunk in 128B row
    const uint32_t asw = (uint32_t)((ac * 16) ^ ((ar & 7) << 4));  // rows differ by 32 -> same
    const size_t agq = __cvta_generic_to_global(A + (size_t)(m0 + ar) * K + ac * 8);

    // ---- B cp.async: 8KB/iter = 4 segs (nb32) x 2KB; thread does 32B ----
    const int seg = tid >> 6;                // 0..3 (nb32 local)
    const int inner = tid & 63;
    const size_t bgq = __cvta_generic_to_global(
        Bp + ((size_t)(n0 / 32 + seg) * kchunks) * 1024 + inner * 32);
    const uint32_t bdst = (uint32_t)(seg * 2048 + inner * 32);

    // ---- A ldmatrix lane addressing ----
    const uint32_t lxor = (uint32_t)((lane & 7) << 4);
    const uint32_t aRow = (uint32_t)((wm * 64 + (lane & 15)) * 128);
    const uint32_t akb = (uint32_t)(((lane >> 4) & 1) * 16);

    float acc[4][4][4];
#pragma unroll
    for (int i = 0; i < 4; ++i)
#pragma unroll
        for (int j = 0; j < 4; ++j)
#pragma unroll
            for (int e = 0; e < 4; ++e) acc[i][j][e] = 0.0f;

    const uint32_t soff[4] = { 0u, 24576u, 49152u, 73728u };

    // stage issue: A tile (64 k-cols) + B bytes (2KB/seg) for iteration ii
    auto issue_stage = [&](int ii, uint32_t so) {
        const int k0 = ii << 6;
#pragma unroll
        for (int j = 0; j < 4; ++j)
            CP_ASYNC16(base + so + (uint32_t)((ar + 32 * j) * 128) + asw,
                       (const void*)(agq + ((size_t)(32 * j) * K + k0) * sizeof(__half)));
        const void* bs = (const void*)(bgq + (size_t)ii * 2048);
        CP_ASYNC16(base + so + 16384u + bdst, bs);
        CP_ASYNC16(base + so + 16384u + bdst + 16u, (const void*)((const char*)bs + 16));
    };

    // ---- prologue: stages 0,1,2 in flight ----
    issue_stage(0, soff[0]); CP_COMMIT();
    issue_stage(1, soff[1]); CP_COMMIT();
    issue_stage(2, soff[2]); CP_COMMIT();

    int p = 0;
    for (int it = 0; it < kIters; ++it) {
        CP_WAIT2();        // stage p's group complete (2 iters of slack)
        __syncthreads();   // visible CTA-wide; stage (p+3)&3 readers done

        if (it + 3 < kIters) issue_stage(it + 3, soff[(p + 3) & 3]);
        CP_COMMIT();       // always commit (possibly empty) to keep group count uniform

        // ---- compute from stage p: 2 k32-blocks x 2 k16-steps ----
        const uint32_t so = soff[p];
        const uint32_t sA = base + so;
        const unsigned char* sB = sptr + so + 16384 + wn * 2048;
#pragma unroll
        for (int kb = 0; kb < 2; ++kb) {
            uint4 q0 = *reinterpret_cast<const uint4*>(sB + kb * 1024 + lane * 16);
            uint4 q1 = *reinterpret_cast<const uint4*>(sB + kb * 1024 + 512 + lane * 16);
#pragma unroll
            for (int h = 0; h < 2; ++h) {
                uint32_t comp[4];
                comp[0] = h ? q0.y : q0.x;
                comp[1] = h ? q0.w : q0.z;
                comp[2] = h ? q1.y : q1.x;
                comp[3] = h ? q1.w : q1.z;
                uint32_t b0[4], b1[4];
#pragma unroll
                for (int nf = 0; nf < 4; ++nf) {
                    b0[nf] = dq8(comp[nf], 0x4140u);
                    b1[nf] = dq8(comp[nf], 0x4342u);
                }
                const int s = kb * 2 + h;
                const uint32_t ca = ((uint32_t)(s * 32) + akb) ^ lxor;
                uint32_t af[4][4];
#pragma unroll
                for (int mf = 0; mf < 4; ++mf)
                    LDMATRIX_X4(af[mf][0], af[mf][1], af[mf][2], af[mf][3],
                                sA + aRow + (uint32_t)(mf * 16 * 128) + ca);
#pragma unroll
                for (int mf = 0; mf < 4; ++mf)
#pragma unroll
                    for (int nf = 0; nf < 4; ++nf)
                        MMA_16816(acc[mf][nf][0], acc[mf][nf][1],
                                  acc[mf][nf][2], acc[mf][nf][3],
                                  af[mf][0], af[mf][1], af[mf][2], af[mf][3],
                                  b0[nf], b1[nf]);
            }
        }
        p = (p + 1) & 3;
    }

    // ---- epilogue ----
    const int lrow0 = wm * 64 + (lane >> 2);          // CTA-local row
    const int lcol0 = wn * 32 + (lane & 3) * 2;       // CTA-local col
    if (MODE == 0) {
        // gelu + scale -> staged half tile (pitch EPI_PITCH, conflict-free) ->
        // one barrier -> fully-coalesced 16B stores (256B rows).
        __half* stg = reinterpret_cast<__half*>(sptr);
#pragma unroll
        for (int nf = 0; nf < 4; ++nf) {
            const int lc = lcol0 + nf * 8;
            const float s0 = __ldg(scales + n0 + lc);
            const float s1 = __ldg(scales + n0 + lc + 1);
#pragma unroll
            for (int mf = 0; mf < 4; ++mf) {
                const int lr = lrow0 + mf * 16;
                float v0 = acc[mf][nf][0] * s0, v1 = acc[mf][nf][1] * s1;
                float v2 = acc[mf][nf][2] * s0, v3 = acc[mf][nf][3] * s1;
                __half2 h0 = __floats2half2_rn(gelu_tanh(v0), gelu_tanh(v1));
                __half2 h1 = __floats2half2_rn(gelu_tanh(v2), gelu_tanh(v3));
                *reinterpret_cast<__half2*>(
                    reinterpret_cast<char*>(stg) + lr * EPI_PITCH + lc * 2) = h0;
                *reinterpret_cast<__half2*>(
                    reinterpret_cast<char*>(stg) + (lr + 8) * EPI_PITCH + lc * 2) = h1;
            }
        }
        __syncthreads();
        // copy: 128 rows x 256B = 2048 chunks of 16B; 8 per thread
#pragma unroll
        for (int j = 0; j < 8; ++j) {
            const int c = tid + j * 256;
            const int row = c >> 4;
            const int off = (c & 15) * 16;   // byte offset in row (16B aligned)
            uint4 v = *reinterpret_cast<const uint4*>(
                reinterpret_cast<const char*>(stg) + row * EPI_PITCH + off);
            *reinterpret_cast<uint4*>(
                reinterpret_cast<char*>(outH + (size_t)(m0 + row) * ldOut + n0) + off) = v;
        }
    } else {
        const int mrow0 = m0 + lrow0;
        const int ncol0 = n0 + lcol0;
#pragma unroll
        for (int nf = 0; nf < 4; ++nf) {
            const int col = ncol0 + nf * 8;
            const float s0 = __ldg(scales + col);
            const float s1 = __ldg(scales + col + 1);
#pragma unroll
            for (int mf = 0; mf < 4; ++mf) {
                const int r = mrow0 + mf * 16;
                *reinterpret_cast<float2*>(outF + (size_t)r * ldOut + col) =
                    make_float2(acc[mf][nf][0] * s0, acc[mf][nf][1] * s1);
                *reinterpret_cast<float2*>(outF + (size_t)(r + 8) * ldOut + col) =
                    make_float2(acc[mf][nf][2] * s0, acc[mf][nf][3] * s1);
            }
        }
    }
}

__global__ void __launch_bounds__(256, 2)
gemm1_kernel(const float* __restrict__ scales) {
    gemm_body<0>(g_Xh, g_W1p, scales, D_MODEL, g_H, nullptr, HIDDEN);
}

__global__ void __launch_bounds__(256, 2)
gemm2_kernel(const float* __restrict__ scales, float* __restrict__ out) {
    gemm_body<1>(g_H, g_W2p, scales, HIDDEN, nullptr, out, D_MODEL);
}

// ---------------------------------------------------------------------------
// Launch
// ---------------------------------------------------------------------------
extern "C" void kernel_launch(void* const* d_in, const int* in_sizes, int n_in,
                              void* d_out, int out_size) {
    const float* x    = (const float*)d_in[0];
    const int*   fc1p = (const int*)d_in[1];
    const float* s1   = (const float*)d_in[2];
    const int*   fc2p = (const int*)d_in[3];
    const float* s2   = (const float*)d_in[4];
    float* out = (float*)d_out;

    cudaFuncSetAttribute(gemm1_kernel, cudaFuncAttributeMaxDynamicSharedMemorySize, SMEM_DYN);
    cudaFuncSetAttribute(gemm2_kernel, cudaFuncAttributeMaxDynamicSharedMemorySize, SMEM_DYN);

    convert_x_kernel<<<(N_TOK * (size_t)D_MODEL) / 4 / 256, 256>>>(x);
    // repack: one thread per output word = N*K/4 words per matrix
    repack_b_kernel<<<((size_t)HIDDEN * D_MODEL / 4) / 256, 256>>>(fc1p, 0, D_MODEL, 7);
    repack_b_kernel<<<((size_t)D_MODEL * HIDDEN / 4) / 256, 256>>>(fc2p, 1, HIDDEN, 9);

    gemm1_kernel<<<dim3(HIDDEN / 128, N_TOK / 128), 256, SMEM_DYN>>>(s1);
    gemm2_kernel<<<dim3(D_MODEL / 128, N_TOK / 128), 256, SMEM_DYN>>>(s2, out);
}